// round 11
// baseline (speedup 1.0000x reference)
#include <cuda_runtime.h>
#include <cstdint>
#include <cstddef>

// 2-layer LSTM: B=32, T=512, IN=2048, H=512, fp32.
// Pipeline: gemm0 -> [reset] rec0 -> gemm1 -> [reset] rec1 (graph-capturable).

typedef unsigned long long ull;

#define Bb 32
#define Tt 512
#define Hh 512
#define Gg 2048          // 4*H
#define Mm 16384         // B*T
#define NBLK 128u

// ---- device scratch (no allocations allowed) -------------------------------
__device__ float g_xgt[(size_t)Tt * Gg * Bb];   // [t][g][b]  128 MB (reused)
__device__ float g_h1[(size_t)Mm * Hh];         // layer-0 output [b*T+t][u]
__device__ float g_ht[2][Hh * Bb];              // hidden state, layout [u][b] (proven)
__device__ unsigned g_bar;
__device__ volatile unsigned g_rel;

// ---- packed f32x2 helpers --------------------------------------------------
__device__ __forceinline__ ull pk(float x, float y) {
    ull r; asm("mov.b64 %0,{%1,%2};" : "=l"(r) : "f"(x), "f"(y)); return r;
}
__device__ __forceinline__ void upk(ull v, float& x, float& y) {
    asm("mov.b64 {%0,%1},%2;" : "=f"(x), "=f"(y) : "l"(v));
}
__device__ __forceinline__ void fma2(ull& d, ull a, ull b) {
    asm("fma.rn.f32x2 %0,%1,%2,%0;" : "+l"(d) : "l"(a), "l"(b));
}
__device__ __forceinline__ float sigf(float x) { return 1.f / (1.f + __expf(-x)); }
__device__ __forceinline__ float tanh_f(float x) {
    float a = fabsf(x);
    float e = __expf(-2.f * a);
    float t = (1.f - e) / (1.f + e);
    return copysignf(t, x);
}

__global__ void reset_bar() { g_bar = 0u; g_rel = 0u; }

// ============================================================================
// GEMM: g_xgt[t][g][b] = A[m][k] @ W[g][k]^T + (b1[g]+b2[g]),  m = b*T+t
// (unchanged — ~90% of f32x2 peak at 888us; leave alone)
// ============================================================================
#define BM 128
#define BN 64
#define BK 16

__global__ __launch_bounds__(256) void gemm_bias(
    const float* __restrict__ A, const float* __restrict__ W,
    const float* __restrict__ b1, const float* __restrict__ b2, int K)
{
    __shared__ float As[BK][BM + 4];
    __shared__ float Bs[BK][BN + 4];
    const int tid = threadIdx.x;
    const int m0 = blockIdx.x * BM;
    const int n0 = blockIdx.y * BN;
    const int tx = tid & 15;
    const int ty = tid >> 4;

    ull acc[8][2];
    #pragma unroll
    for (int i = 0; i < 8; i++) { acc[i][0] = 0ull; acc[i][1] = 0ull; }

    for (int kt = 0; kt < K; kt += BK) {
        #pragma unroll
        for (int r = 0; r < 2; r++) {
            int f = tid + r * 256;
            int m = f >> 2, k4 = (f & 3) * 4;
            float4 v = *(const float4*)(A + (size_t)(m0 + m) * K + kt + k4);
            As[k4 + 0][m] = v.x; As[k4 + 1][m] = v.y;
            As[k4 + 2][m] = v.z; As[k4 + 3][m] = v.w;
        }
        {
            int n = tid >> 2, k4 = (tid & 3) * 4;
            float4 v = *(const float4*)(W + (size_t)(n0 + n) * K + kt + k4);
            Bs[k4 + 0][n] = v.x; Bs[k4 + 1][n] = v.y;
            Bs[k4 + 2][n] = v.z; Bs[k4 + 3][n] = v.w;
        }
        __syncthreads();
        #pragma unroll
        for (int kk = 0; kk < BK; kk++) {
            float4 a0 = *(const float4*)&As[kk][ty * 8];
            float4 a1 = *(const float4*)&As[kk][ty * 8 + 4];
            ulonglong2 bv = *(const ulonglong2*)&Bs[kk][tx * 4];
            float av[8] = {a0.x, a0.y, a0.z, a0.w, a1.x, a1.y, a1.z, a1.w};
            #pragma unroll
            for (int i = 0; i < 8; i++) {
                ull d = pk(av[i], av[i]);
                fma2(acc[i][0], d, bv.x);
                fma2(acc[i][1], d, bv.y);
            }
        }
        __syncthreads();
    }

    float bias[4];
    #pragma unroll
    for (int c = 0; c < 4; c++) { int g = n0 + tx * 4 + c; bias[c] = b1[g] + b2[g]; }
    #pragma unroll
    for (int i = 0; i < 8; i++) {
        int m = m0 + ty * 8 + i;
        int b = m >> 9, t = m & 511;
        #pragma unroll
        for (int j = 0; j < 2; j++) {
            float v0, v1; upk(acc[i][j], v0, v1);
            int g = n0 + tx * 4 + j * 2;
            g_xgt[((size_t)t * Gg + g) * Bb + b]     = v0 + bias[j * 2];
            g_xgt[((size_t)t * Gg + g + 1) * Bb + b] = v1 + bias[j * 2 + 1];
        }
    }
}

// ============================================================================
// Persistent recurrence: 128 blocks x 256 threads, atomic grid barrier
// (proven R8 protocol). Serial-chain cuts:
//  - warp-private h staging: warp w stages [u0k..u0k+64) x all 32 b (contiguous
//    8KB in [u][b]) into its own smem slice; __syncwarp; compute. No block bar.
//  - writers-only __threadfence before the barrier.
//  - xg prefetch for t+1 issued before the grid barrier (L2 latency overlapped).
// Compute per lane (R8 tiling): rows rg*4..+3, pairs p8 & p8+8, 64-k chunk.
// ============================================================================
#define HS2 514                          // w4 row stride (ull)
#define SLICE (16 * 66)                  // warp slice: 16 pairs x 66 ull
#define SM_HW   (8 * SLICE * 8)          // 67584
#define SM_W4   (16 * HS2 * 8)           // 65792
#define SM_PART (8 * 16 * 16 * 8)        // 16384
#define SMEM_REC (SM_HW + SM_W4 + SM_PART)

__global__ __launch_bounds__(256) void lstm_rec(
    const float* __restrict__ Whh, float* __restrict__ hseq)
{
    extern __shared__ char smraw[];
    ull* hw   = (ull*)smraw;                        // 8 warp slices [pair][du]
    ull* w4   = (ull*)(smraw + SM_HW);              // [row r][k]  (w,w)
    ull* part = (ull*)(smraw + SM_HW + SM_W4);      // [kc][r][p]
    float* partf = (float*)part;

    const int tid  = threadIdx.x;
    const int w    = tid >> 5;
    const int lane = tid & 31;
    const int bid  = blockIdx.x;
    const int u0   = bid * 4;

    const int p8 = lane & 7;                        // batch-pairs p8, p8+8
    const int rg = lane >> 3;                       // rows rg*4 .. rg*4+3
    const int k0 = w * 64;                          // k-chunk per warp
    ull* sl = hw + w * SLICE;                       // this warp's h slice

    // ---- init: pack W_hh rows (duplicated pairs) into smem ----
    for (int i = tid; i < 16 * Hh; i += 256) {
        int r = i >> 9, k = i & 511;
        int gr = (r >> 2) * Hh + u0 + (r & 3);
        float v = Whh[(size_t)gr * Hh + k];
        w4[r * HS2 + k] = pk(v, v);
    }
    // zero own slice of h state (layout [u][b])
    if (tid < 128) g_ht[0][(u0 + (tid >> 5)) * Bb + (tid & 31)] = 0.f;

    // pointwise ownership: tid<128 owns unit pu, batch pb; c in register
    const int pu = tid >> 5;
    const int pb = tid & 31;
    float c = 0.f;

    __syncthreads();
    unsigned bi = 1;
    if (tid == 0) {                                 // barrier 0: zeros visible
        __threadfence();
        unsigned old = atomicAdd(&g_bar, 1u);
        if (old == NBLK * bi - 1u) g_rel = bi;
        while (g_rel < bi) {}
        __threadfence();
    }
    __syncthreads();
    bi++;

    // xg prefetch for t=0
    float xv0 = 0.f, xv1 = 0.f, xv2 = 0.f, xv3 = 0.f;
    if (tid < 128) {
        const float* xb = g_xgt + ((size_t)u0 + pu) * Bb + pb;
        xv0 = __ldg(xb);
        xv1 = __ldg(xb + (size_t)Hh * Bb);
        xv2 = __ldg(xb + (size_t)2 * Hh * Bb);
        xv3 = __ldg(xb + (size_t)3 * Hh * Bb);
    }

    for (int t = 0; t < Tt; t++) {
        // ---- warp-private stage: units [k0,k0+64) x 32 b -> slice (pairs) ----
        const float4* hb4 = (const float4*)(g_ht[t & 1]) + k0 * 8;
        #pragma unroll
        for (int i = 0; i < 16; i++) {
            int idx = i * 32 + lane;                // 0..511 float4 in chunk
            float4 v = __ldcg(hb4 + idx);
            int du = idx >> 3;                      // unit offset 0..63
            int pr = (idx & 7) * 2;                 // pair index
            sl[pr * 66 + du]       = pk(v.x, v.y);
            sl[(pr + 1) * 66 + du] = pk(v.z, v.w);
        }
        __syncwarp();

        // ---- partials: 4 rows x 2 pairs x 64 k per lane ----
        ull a00 = 0, a01 = 0, a10 = 0, a11 = 0;
        ull a20 = 0, a21 = 0, a30 = 0, a31 = 0;
        const ull* hp0 = sl + p8 * 66;
        const ull* hp1 = sl + (p8 + 8) * 66;
        const ull* wq0 = w4 + (rg * 4 + 0) * HS2 + k0;
        const ull* wq1 = w4 + (rg * 4 + 1) * HS2 + k0;
        const ull* wq2 = w4 + (rg * 4 + 2) * HS2 + k0;
        const ull* wq3 = w4 + (rg * 4 + 3) * HS2 + k0;
        #pragma unroll 2
        for (int kk = 0; kk < 64; kk += 2) {
            ulonglong2 h0 = *(const ulonglong2*)(hp0 + kk);
            ulonglong2 h1 = *(const ulonglong2*)(hp1 + kk);
            ulonglong2 w0 = *(const ulonglong2*)(wq0 + kk);
            ulonglong2 w1 = *(const ulonglong2*)(wq1 + kk);
            ulonglong2 w2 = *(const ulonglong2*)(wq2 + kk);
            ulonglong2 w3 = *(const ulonglong2*)(wq3 + kk);
            fma2(a00, h0.x, w0.x); fma2(a01, h1.x, w0.x);
            fma2(a10, h0.x, w1.x); fma2(a11, h1.x, w1.x);
            fma2(a20, h0.x, w2.x); fma2(a21, h1.x, w2.x);
            fma2(a30, h0.x, w3.x); fma2(a31, h1.x, w3.x);
            fma2(a00, h0.y, w0.y); fma2(a01, h1.y, w0.y);
            fma2(a10, h0.y, w1.y); fma2(a11, h1.y, w1.y);
            fma2(a20, h0.y, w2.y); fma2(a21, h1.y, w2.y);
            fma2(a30, h0.y, w3.y); fma2(a31, h1.y, w3.y);
        }
        {
            // part[kc=w][r][p]: pp4[j*16] = row rg*4+j pair p8; +8 = pair p8+8
            ull* pp4 = part + ((size_t)w * 16 + rg * 4) * 16 + p8;
            pp4[0]  = a00; pp4[8]  = a01;
            pp4[16] = a10; pp4[24] = a11;
            pp4[32] = a20; pp4[40] = a21;
            pp4[48] = a30; pp4[56] = a31;
        }
        __syncthreads();

        // ---- reduce + activations + cell update (tid<128) ----
        float nxv0 = 0.f, nxv1 = 0.f, nxv2 = 0.f, nxv3 = 0.f;
        if (tid < 128) {
            float pre[4] = {xv0, xv1, xv2, xv3};
            #pragma unroll
            for (int g = 0; g < 4; g++) {
                int r = g * 4 + pu;
                #pragma unroll
                for (int q = 0; q < 8; q++)
                    pre[g] += partf[(q * 16 + r) * 32 + pb];
            }
            float iv = sigf(pre[0]);
            float fv = sigf(pre[1]);
            float gv = tanh_f(pre[2]);
            float ov = sigf(pre[3]);
            c = fv * c + iv * gv;
            float h = ov * tanh_f(c);
            hseq[((size_t)pb * Tt + t) * Hh + u0 + pu] = h;     // [B][T][H]
            g_ht[(t + 1) & 1][(u0 + pu) * Bb + pb] = h;
            __threadfence();       // writer drains h before its block arrives
            if (t + 1 < Tt) {      // prefetch xg(t+1): overlaps the barrier
                const float* xb = g_xgt + ((size_t)(t + 1) * Gg + u0 + pu) * Bb + pb;
                nxv0 = __ldg(xb);
                nxv1 = __ldg(xb + (size_t)Hh * Bb);
                nxv2 = __ldg(xb + (size_t)2 * Hh * Bb);
                nxv3 = __ldg(xb + (size_t)3 * Hh * Bb);
            }
        }
        __syncthreads();

        // ---- grid barrier (proven protocol) ----
        if (tid == 0) {
            unsigned old = atomicAdd(&g_bar, 1u);
            if (old == NBLK * bi - 1u) g_rel = bi;
            while (g_rel < bi) {}
            __threadfence();
        }
        __syncthreads();
        bi++;
        xv0 = nxv0; xv1 = nxv1; xv2 = nxv2; xv3 = nxv3;
    }
}

// ============================================================================
extern "C" void kernel_launch(void* const* d_in, const int* in_sizes, int n_in,
                              void* d_out, int out_size)
{
    const float* feats = (const float*)d_in[0];
    const float* Wih0  = (const float*)d_in[1];
    const float* Whh0  = (const float*)d_in[2];
    const float* bih0  = (const float*)d_in[3];
    const float* bhh0  = (const float*)d_in[4];
    const float* Wih1  = (const float*)d_in[5];
    const float* Whh1  = (const float*)d_in[6];
    const float* bih1  = (const float*)d_in[7];
    const float* bhh1  = (const float*)d_in[8];
    float* out = (float*)d_out;

    cudaFuncSetAttribute(lstm_rec, cudaFuncAttributeMaxDynamicSharedMemorySize, SMEM_REC);

    float* h1_ptr = nullptr;
    cudaGetSymbolAddress((void**)&h1_ptr, g_h1);

    dim3 ggrid(Mm / BM, Gg / BN);  // (128, 32)

    gemm_bias<<<ggrid, 256>>>(feats, Wih0, bih0, bhh0, 2048);
    reset_bar<<<1, 1>>>();
    lstm_rec<<<128, 256, SMEM_REC>>>(Whh0, h1_ptr);

    gemm_bias<<<ggrid, 256>>>(h1_ptr, Wih1, bih1, bhh1, 512);
    reset_bar<<<1, 1>>>();
    lstm_rec<<<128, 256, SMEM_REC>>>(Whh1, out);
}